// round 1
// baseline (speedup 1.0000x reference)
#include <cuda_runtime.h>

#define BS 16
#define SS 2048
#define HH 1024
#define DD 32
#define CC 8
#define LL 3
#define NSPAN (BS * DD)   // 512

// scratch for logits so the loss kernel can read them regardless of out layout
__device__ float g_logits[NSPAN * LL];

// Detect whether an "int" input array is actually int64 (little-endian):
// for small non-negative values, every odd 32-bit word (the high halves) is 0.
// For the int32 layout those words are real data (head/tail are nonzero
// multiples of 64; discourse/labels are 256 random values — P(all zero) ~ 0).
__device__ __forceinline__ bool detect_i64(const int* w, int nwords) {
    for (int i = 1; i < nwords; i += 2)
        if (w[i] != 0) return false;
    return true;
}

__device__ __forceinline__ int load_int(const void* p, int i, bool is64) {
    if (is64) return (int)((const long long*)p)[i];
    return ((const int*)p)[i];
}

// One block per (b, d) span. 256 threads, each owns 4 contiguous h (float4).
// Streams the 63 span rows (coalesced), accumulates column sums, then the
// per-class GEMV (H x 3) via warp-shuffle + smem reduction.
__global__ void __launch_bounds__(256)
pool_logits_kernel(const float* __restrict__ enc,
                   const float* __restrict__ W,
                   const float* __restrict__ bias,
                   const void* __restrict__ headp,
                   const void* __restrict__ tailp,
                   const void* __restrict__ dtp,
                   float* __restrict__ d_out, int out_size)
{
    __shared__ int s_meta[3];           // s0, n, c
    const int span = blockIdx.x;        // 0..511
    const int t    = threadIdx.x;       // 0..255

    if (t == 0) {
        bool h64 = detect_i64((const int*)headp, NSPAN);
        bool t64 = detect_i64((const int*)tailp, NSPAN);
        bool c64 = detect_i64((const int*)dtp,   NSPAN);
        int s0 = load_int(headp, span, h64) + 1;   // mask starts at head+1
        int s1 = load_int(tailp, span, t64);       // exclusive end
        s_meta[0] = s0;
        s_meta[1] = s1 - s0;                       // = 63
        s_meta[2] = load_int(dtp, span, c64);
    }
    __syncthreads();

    const int s0 = s_meta[0];
    const int n  = s_meta[1];
    const int c  = s_meta[2];
    const int b  = span / DD;

    const float4* base =
        (const float4*)(enc + ((size_t)b * SS + (size_t)s0) * HH) + t;
    const int rowstep = HH / 4;  // float4 units per row

    float4 acc = make_float4(0.f, 0.f, 0.f, 0.f);
    int i = 0;
    // unroll-by-4 for MLP (4 independent in-flight LDG.128 per thread)
    for (; i + 4 <= n; i += 4) {
        float4 v0 = __ldg(base + (size_t)(i + 0) * rowstep);
        float4 v1 = __ldg(base + (size_t)(i + 1) * rowstep);
        float4 v2 = __ldg(base + (size_t)(i + 2) * rowstep);
        float4 v3 = __ldg(base + (size_t)(i + 3) * rowstep);
        acc.x += (v0.x + v1.x) + (v2.x + v3.x);
        acc.y += (v0.y + v1.y) + (v2.y + v3.y);
        acc.z += (v0.z + v1.z) + (v2.z + v3.z);
        acc.w += (v0.w + v1.w) + (v2.w + v3.w);
    }
    for (; i < n; i++) {
        float4 v = __ldg(base + (size_t)i * rowstep);
        acc.x += v.x; acc.y += v.y; acc.z += v.z; acc.w += v.w;
    }

    const float inv = 1.0f / (float)n;
    const float p0 = acc.x * inv, p1 = acc.y * inv;
    const float p2 = acc.z * inv, p3 = acc.w * inv;

    const int h0 = t * 4;
    const float* Wc = W + (size_t)c * HH * LL;

    float l0 = p0 * __ldg(&Wc[(h0 + 0) * LL + 0]) + p1 * __ldg(&Wc[(h0 + 1) * LL + 0])
             + p2 * __ldg(&Wc[(h0 + 2) * LL + 0]) + p3 * __ldg(&Wc[(h0 + 3) * LL + 0]);
    float l1 = p0 * __ldg(&Wc[(h0 + 0) * LL + 1]) + p1 * __ldg(&Wc[(h0 + 1) * LL + 1])
             + p2 * __ldg(&Wc[(h0 + 2) * LL + 1]) + p3 * __ldg(&Wc[(h0 + 3) * LL + 1]);
    float l2 = p0 * __ldg(&Wc[(h0 + 0) * LL + 2]) + p1 * __ldg(&Wc[(h0 + 1) * LL + 2])
             + p2 * __ldg(&Wc[(h0 + 2) * LL + 2]) + p3 * __ldg(&Wc[(h0 + 3) * LL + 2]);

    // intra-warp reduce
    #pragma unroll
    for (int o = 16; o > 0; o >>= 1) {
        l0 += __shfl_down_sync(0xffffffffu, l0, o);
        l1 += __shfl_down_sync(0xffffffffu, l1, o);
        l2 += __shfl_down_sync(0xffffffffu, l2, o);
    }

    __shared__ float sred[8][3];
    const int w = t >> 5, lane = t & 31;
    if (lane == 0) { sred[w][0] = l0; sred[w][1] = l1; sred[w][2] = l2; }
    __syncthreads();

    if (t < LL) {
        float s = 0.f;
        #pragma unroll
        for (int k = 0; k < 8; k++) s += sred[k][t];
        s += __ldg(&bias[c * LL + t]);
        g_logits[span * LL + t] = s;
        if (out_size >= NSPAN * LL)          // logits occupy the front of out
            d_out[span * LL + t] = s;
    }
}

// One block, one thread per span: log-softmax over L=3, NLL, valid-masked mean.
__global__ void __launch_bounds__(NSPAN)
loss_kernel(const void* __restrict__ labp, float* __restrict__ d_out, int out_size)
{
    const int t = threadIdx.x;  // 0..511 == span
    __shared__ float s_nll[NSPAN];
    __shared__ float s_v[NSPAN];
    __shared__ int   s_is64;

    if (t == 0) s_is64 = detect_i64((const int*)labp, NSPAN) ? 1 : 0;
    __syncthreads();

    const int lab = load_int(labp, t, s_is64 != 0);

    const float x0 = g_logits[t * LL + 0];
    const float x1 = g_logits[t * LL + 1];
    const float x2 = g_logits[t * LL + 2];

    const float m   = fmaxf(x0, fmaxf(x1, x2));
    const float lse = m + logf(expf(x0 - m) + expf(x1 - m) + expf(x2 - m));

    const bool valid = (lab >= 0);
    const float xl = valid ? ((lab == 0) ? x0 : ((lab == 1) ? x1 : x2)) : 0.f;

    s_nll[t] = valid ? (lse - xl) : 0.f;
    s_v[t]   = valid ? 1.f : 0.f;
    __syncthreads();

    for (int o = NSPAN / 2; o > 0; o >>= 1) {
        if (t < o) { s_nll[t] += s_nll[t + o]; s_v[t] += s_v[t + o]; }
        __syncthreads();
    }

    if (t == 0) {
        const float loss = s_nll[0] / s_v[0];
        if (out_size >= NSPAN * LL + 1)      d_out[NSPAN * LL] = loss;  // (logits, loss)
        else if (out_size < NSPAN * LL)      d_out[0] = loss;           // loss-only fallback
    }
}

extern "C" void kernel_launch(void* const* d_in, const int* in_sizes, int n_in,
                              void* d_out, int out_size)
{
    const float* enc  = (const float*)d_in[0];   // encoder_layer (BS,S,H) f32
    const float* W    = (const float*)d_in[1];   // (C,H,L) f32
    const float* bias = (const float*)d_in[2];   // (C,L)   f32
    const void*  head = d_in[3];                 // (BS,D) int32 or int64
    const void*  tail = d_in[4];
    const void*  dtid = d_in[5];
    const void*  labs = d_in[6];

    float* out = (float*)d_out;

    pool_logits_kernel<<<NSPAN, 256>>>(enc, W, bias, head, tail, dtid, out, out_size);
    loss_kernel<<<1, NSPAN>>>(labs, out, out_size);
}

// round 2
// speedup vs baseline: 1.0517x; 1.0517x over previous
#include <cuda_runtime.h>

#define BS 16
#define SS 2048
#define HH 1024
#define DD 32
#define CC 8
#define LL 3
#define NSPAN (BS * DD)     // 512
#define NBLK  (NSPAN * 2)   // 1024 — two half-span blocks per span

// partial logits per block (block = 2*span + half), written every launch
__device__ float g_part[NBLK * LL];

__device__ __forceinline__ int load_int(const void* p, int i, bool is64) {
    if (is64) return (int)((const long long*)p)[i];
    return ((const int*)p)[i];
}

// Kernel 1: grid = 1024, block = 256. Block (2*span + half) streams ~half of
// the span's 63 rows (full-row coalesced, each thread owns 4 contiguous h),
// accumulates column sums, then a partial GEMV against W[c] (H x 3).
// Partial logits (un-normalized, no bias) go to g_part.
__global__ void __launch_bounds__(256)
pool_kernel(const float* __restrict__ enc,
            const float* __restrict__ W,
            const void* __restrict__ headp,
            const void* __restrict__ tailp,
            const void* __restrict__ dtp)
{
    const int blk  = blockIdx.x;
    const int span = blk >> 1;
    const int half = blk & 1;
    const int t    = threadIdx.x;      // 0..255

    // ---- parallel int32-vs-int64 detection (one odd-word check per thread) ----
    __shared__ int s_flags;
    if (t == 0) s_flags = 0;
    __syncthreads();
    {
        const int w = 2 * t + 1;       // odd words 1..511
        int f = 0;
        if (((const int*)headp)[w]) f |= 1;
        if (((const int*)tailp)[w]) f |= 2;
        if (((const int*)dtp)[w])   f |= 4;
        if (f) atomicOr(&s_flags, f);
    }
    __syncthreads();
    const bool h64 = !(s_flags & 1);
    const bool t64 = !(s_flags & 2);
    const bool c64 = !(s_flags & 4);

    const int s0 = load_int(headp, span, h64) + 1;     // mask starts at head+1
    const int n  = load_int(tailp, span, t64) - s0;    // typically 63
    const int c  = load_int(dtp,   span, c64);
    const int b  = span / DD;

    // this half's row range
    const int hn = (n + 1) >> 1;
    const int r0 = half * hn;
    const int r1 = (r0 + hn < n) ? (r0 + hn) : n;

    const float4* base =
        (const float4*)(enc + ((size_t)b * SS + (size_t)(s0 + r0)) * HH) + t;
    const int rowstep = HH / 4;
    const int nr = r1 - r0;

    float4 acc = make_float4(0.f, 0.f, 0.f, 0.f);
    int i = 0;
    for (; i + 4 <= nr; i += 4) {     // 4 independent LDG.128 in flight
        float4 v0 = __ldcs(base + (size_t)(i + 0) * rowstep);
        float4 v1 = __ldcs(base + (size_t)(i + 1) * rowstep);
        float4 v2 = __ldcs(base + (size_t)(i + 2) * rowstep);
        float4 v3 = __ldcs(base + (size_t)(i + 3) * rowstep);
        acc.x += (v0.x + v1.x) + (v2.x + v3.x);
        acc.y += (v0.y + v1.y) + (v2.y + v3.y);
        acc.z += (v0.z + v1.z) + (v2.z + v3.z);
        acc.w += (v0.w + v1.w) + (v2.w + v3.w);
    }
    for (; i < nr; i++) {
        float4 v = __ldcs(base + (size_t)i * rowstep);
        acc.x += v.x; acc.y += v.y; acc.z += v.z; acc.w += v.w;
    }

    // partial GEMV against W[c] (no 1/n, no bias — linear, applied at combine)
    const int h0 = t * 4;
    const float* Wc = W + (size_t)c * HH * LL;

    float l0 = acc.x * __ldg(&Wc[(h0 + 0) * LL + 0]) + acc.y * __ldg(&Wc[(h0 + 1) * LL + 0])
             + acc.z * __ldg(&Wc[(h0 + 2) * LL + 0]) + acc.w * __ldg(&Wc[(h0 + 3) * LL + 0]);
    float l1 = acc.x * __ldg(&Wc[(h0 + 0) * LL + 1]) + acc.y * __ldg(&Wc[(h0 + 1) * LL + 1])
             + acc.z * __ldg(&Wc[(h0 + 2) * LL + 1]) + acc.w * __ldg(&Wc[(h0 + 3) * LL + 1]);
    float l2 = acc.x * __ldg(&Wc[(h0 + 0) * LL + 2]) + acc.y * __ldg(&Wc[(h0 + 1) * LL + 2])
             + acc.z * __ldg(&Wc[(h0 + 2) * LL + 2]) + acc.w * __ldg(&Wc[(h0 + 3) * LL + 2]);

    #pragma unroll
    for (int o = 16; o > 0; o >>= 1) {
        l0 += __shfl_down_sync(0xffffffffu, l0, o);
        l1 += __shfl_down_sync(0xffffffffu, l1, o);
        l2 += __shfl_down_sync(0xffffffffu, l2, o);
    }

    __shared__ float sred[8][3];
    const int w = t >> 5, lane = t & 31;
    if (lane == 0) { sred[w][0] = l0; sred[w][1] = l1; sred[w][2] = l2; }
    __syncthreads();

    if (t < LL) {
        float s = 0.f;
        #pragma unroll
        for (int k = 0; k < 8; k++) s += sred[k][t];
        g_part[blk * LL + t] = s;
    }
}

// Kernel 2: 1 block, 512 threads (one per span). Combines the two half-span
// partial logits, normalizes, adds bias, writes logits, computes NLL loss
// via warp-shuffle reduction.
__global__ void __launch_bounds__(NSPAN)
combine_loss_kernel(const float* __restrict__ bias,
                    const void* __restrict__ headp,
                    const void* __restrict__ tailp,
                    const void* __restrict__ dtp,
                    const void* __restrict__ labp,
                    float* __restrict__ d_out, int out_size)
{
    const int t = threadIdx.x;   // 0..511 == span

    // ---- parallel detection for all four index arrays ----
    __shared__ int s_flags;
    if (t == 0) s_flags = 0;
    __syncthreads();
    if (t < 256) {
        const int w = 2 * t + 1;
        int f = 0;
        if (((const int*)headp)[w]) f |= 1;
        if (((const int*)tailp)[w]) f |= 2;
        if (((const int*)dtp)[w])   f |= 4;
        if (((const int*)labp)[w])  f |= 8;
        if (f) atomicOr(&s_flags, f);
    }
    __syncthreads();
    const bool h64 = !(s_flags & 1);
    const bool t64 = !(s_flags & 2);
    const bool c64 = !(s_flags & 4);
    const bool l64 = !(s_flags & 8);

    const int s0  = load_int(headp, t, h64) + 1;
    const int n   = load_int(tailp, t, t64) - s0;
    const int c   = load_int(dtp,   t, c64);
    const int lab = load_int(labp,  t, l64);

    const float inv = 1.0f / (float)n;
    const float b0 = __ldg(&bias[c * LL + 0]);
    const float b1 = __ldg(&bias[c * LL + 1]);
    const float b2 = __ldg(&bias[c * LL + 2]);

    const float* pa = &g_part[(2 * t) * LL];
    const float* pb = &g_part[(2 * t + 1) * LL];
    const float x0 = (pa[0] + pb[0]) * inv + b0;
    const float x1 = (pa[1] + pb[1]) * inv + b1;
    const float x2 = (pa[2] + pb[2]) * inv + b2;

    if (out_size >= NSPAN * LL) {
        d_out[t * LL + 0] = x0;
        d_out[t * LL + 1] = x1;
        d_out[t * LL + 2] = x2;
    }

    const float m   = fmaxf(x0, fmaxf(x1, x2));
    const float lse = m + logf(expf(x0 - m) + expf(x1 - m) + expf(x2 - m));
    const bool valid = (lab >= 0);
    const float xl = valid ? ((lab == 0) ? x0 : ((lab == 1) ? x1 : x2)) : 0.f;

    float nll = valid ? (lse - xl) : 0.f;
    float vf  = valid ? 1.f : 0.f;

    // warp-shuffle reduce (16 warps)
    #pragma unroll
    for (int o = 16; o > 0; o >>= 1) {
        nll += __shfl_down_sync(0xffffffffu, nll, o);
        vf  += __shfl_down_sync(0xffffffffu, vf,  o);
    }
    __shared__ float s_n[16], s_v[16];
    const int w = t >> 5, lane = t & 31;
    if (lane == 0) { s_n[w] = nll; s_v[w] = vf; }
    __syncthreads();

    if (w == 0) {
        float a = (lane < 16) ? s_n[lane] : 0.f;
        float v = (lane < 16) ? s_v[lane] : 0.f;
        #pragma unroll
        for (int o = 8; o > 0; o >>= 1) {
            a += __shfl_down_sync(0xffffffffu, a, o);
            v += __shfl_down_sync(0xffffffffu, v, o);
        }
        if (lane == 0) {
            const float loss = a / v;
            if (out_size >= NSPAN * LL + 1)  d_out[NSPAN * LL] = loss;
            else if (out_size < NSPAN * LL)  d_out[0] = loss;
        }
    }
}

extern "C" void kernel_launch(void* const* d_in, const int* in_sizes, int n_in,
                              void* d_out, int out_size)
{
    const float* enc  = (const float*)d_in[0];   // encoder_layer (BS,S,H) f32
    const float* W    = (const float*)d_in[1];   // (C,H,L) f32
    const float* bias = (const float*)d_in[2];   // (C,L)   f32
    const void*  head = d_in[3];                 // (BS,D) int32 or int64
    const void*  tail = d_in[4];
    const void*  dtid = d_in[5];
    const void*  labs = d_in[6];

    float* out = (float*)d_out;

    pool_kernel<<<NBLK, 256>>>(enc, W, head, tail, dtid);
    combine_loss_kernel<<<1, NSPAN>>>(bias, head, tail, dtid, labs, out, out_size);
}

// round 3
// speedup vs baseline: 1.0609x; 1.0087x over previous
#include <cuda_runtime.h>

#define BS 16
#define SS 2048
#define HH 1024
#define DD 32
#define CC 8
#define LL 3
#define NSPAN (BS * DD)     // 512
#define NBLK  (NSPAN * 2)   // 1024 — two half-span blocks per span

// partial logits per block (block = 2*span + half), rewritten every launch
__device__ float g_part[NBLK * LL];
// completion counter for last-block-done combine (reset to 0 by the tail block)
__device__ unsigned int g_count = 0;

__device__ __forceinline__ int load_int(const void* p, int i, bool is64) {
    if (is64) return (int)((const long long*)p)[i];
    return ((const int*)p)[i];
}

// Fused kernel: grid = 1024, block = 256.
// Phase 1 (all blocks): block (2*span + half) streams ~half of the span's 63
//   rows (coalesced; thread owns 4 contiguous h), accumulates column sums,
//   partial GEMV vs W[c] (H x 3), writes 3 partial logits to g_part.
// Phase 2 (last block to finish): combines halves, normalizes, adds bias,
//   writes logits + NLL loss.
__global__ void __launch_bounds__(256, 8)
fused_kernel(const float* __restrict__ enc,
             const float* __restrict__ W,
             const float* __restrict__ bias,
             const void* __restrict__ headp,
             const void* __restrict__ tailp,
             const void* __restrict__ dtp,
             const void* __restrict__ labp,
             float* __restrict__ d_out, int out_size)
{
    const int blk  = blockIdx.x;
    const int span = blk >> 1;
    const int half = blk & 1;
    const int t    = threadIdx.x;      // 0..255

    // ---- parallel int32-vs-int64 layout detection (odd high-words all zero) ----
    __shared__ int s_flags;
    if (t == 0) s_flags = 0;
    __syncthreads();
    {
        const int w = 2 * t + 1;       // odd words 1..511
        int f = 0;
        if (((const int*)headp)[w]) f |= 1;
        if (((const int*)tailp)[w]) f |= 2;
        if (((const int*)dtp)[w])   f |= 4;
        if (((const int*)labp)[w])  f |= 8;
        if (f) atomicOr(&s_flags, f);
    }
    __syncthreads();
    const int flags = s_flags;
    const bool h64 = !(flags & 1);
    const bool t64 = !(flags & 2);
    const bool c64 = !(flags & 4);
    const bool l64 = !(flags & 8);

    const int s0 = load_int(headp, span, h64) + 1;     // mask starts at head+1
    const int n  = load_int(tailp, span, t64) - s0;    // typically 63
    const int c  = load_int(dtp,   span, c64);
    const int b  = span / DD;

    // this half's row range
    const int hn = (n + 1) >> 1;
    const int r0 = half * hn;
    const int r1 = (r0 + hn < n) ? (r0 + hn) : n;
    const int nr = r1 - r0;

    const float4* base =
        (const float4*)(enc + ((size_t)b * SS + (size_t)(s0 + r0)) * HH) + t;
    const int rowstep = HH / 4;

    float4 acc = make_float4(0.f, 0.f, 0.f, 0.f);
    int i = 0;
    for (; i + 4 <= nr; i += 4) {      // 4 independent LDG.128 in flight
        float4 v0 = __ldcs(base + (size_t)(i + 0) * rowstep);
        float4 v1 = __ldcs(base + (size_t)(i + 1) * rowstep);
        float4 v2 = __ldcs(base + (size_t)(i + 2) * rowstep);
        float4 v3 = __ldcs(base + (size_t)(i + 3) * rowstep);
        acc.x += (v0.x + v1.x) + (v2.x + v3.x);
        acc.y += (v0.y + v1.y) + (v2.y + v3.y);
        acc.z += (v0.z + v1.z) + (v2.z + v3.z);
        acc.w += (v0.w + v1.w) + (v2.w + v3.w);
    }
    for (; i < nr; i++) {
        float4 v = __ldcs(base + (size_t)i * rowstep);
        acc.x += v.x; acc.y += v.y; acc.z += v.z; acc.w += v.w;
    }

    // partial GEMV against W[c] (un-normalized, no bias — linear)
    const int h0 = t * 4;
    const float* Wc = W + (size_t)c * HH * LL;

    float l0 = acc.x * __ldg(&Wc[(h0 + 0) * LL + 0]) + acc.y * __ldg(&Wc[(h0 + 1) * LL + 0])
             + acc.z * __ldg(&Wc[(h0 + 2) * LL + 0]) + acc.w * __ldg(&Wc[(h0 + 3) * LL + 0]);
    float l1 = acc.x * __ldg(&Wc[(h0 + 0) * LL + 1]) + acc.y * __ldg(&Wc[(h0 + 1) * LL + 1])
             + acc.z * __ldg(&Wc[(h0 + 2) * LL + 1]) + acc.w * __ldg(&Wc[(h0 + 3) * LL + 1]);
    float l2 = acc.x * __ldg(&Wc[(h0 + 0) * LL + 2]) + acc.y * __ldg(&Wc[(h0 + 1) * LL + 2])
             + acc.z * __ldg(&Wc[(h0 + 2) * LL + 2]) + acc.w * __ldg(&Wc[(h0 + 3) * LL + 2]);

    #pragma unroll
    for (int o = 16; o > 0; o >>= 1) {
        l0 += __shfl_down_sync(0xffffffffu, l0, o);
        l1 += __shfl_down_sync(0xffffffffu, l1, o);
        l2 += __shfl_down_sync(0xffffffffu, l2, o);
    }

    __shared__ float sred[8][3];
    {
        const int w = t >> 5, lane = t & 31;
        if (lane == 0) { sred[w][0] = l0; sred[w][1] = l1; sred[w][2] = l2; }
    }
    __syncthreads();

    if (t < LL) {
        float s = 0.f;
        #pragma unroll
        for (int k = 0; k < 8; k++) s += sred[k][t];
        g_part[blk * LL + t] = s;
    }

    // ---- last-block-done: elect the final block to combine ----
    __shared__ int s_last;
    __threadfence();                   // publish g_part before signaling
    __syncthreads();                   // all warps' writes included
    if (t == 0) {
        unsigned int prev = atomicAdd(&g_count, 1u);
        s_last = (prev == NBLK - 1) ? 1 : 0;
    }
    __syncthreads();
    if (!s_last) return;

    if (t == 0) g_count = 0;           // reset for next graph replay

    // ---- Phase 2: combine + loss (one block, 256 threads, 2 spans each) ----
    float nll = 0.f, vf = 0.f;
    #pragma unroll
    for (int k = 0; k < 2; k++) {
        const int sp = t + k * 256;    // span 0..511

        const int ss0 = load_int(headp, sp, h64) + 1;
        const int sn  = load_int(tailp, sp, t64) - ss0;
        const int sc  = load_int(dtp,   sp, c64);
        const int lab = load_int(labp,  sp, l64);

        const float inv = 1.0f / (float)sn;
        const float* pa = &g_part[(2 * sp) * LL];
        const float* pb = &g_part[(2 * sp + 1) * LL];
        const float x0 = (pa[0] + pb[0]) * inv + __ldg(&bias[sc * LL + 0]);
        const float x1 = (pa[1] + pb[1]) * inv + __ldg(&bias[sc * LL + 1]);
        const float x2 = (pa[2] + pb[2]) * inv + __ldg(&bias[sc * LL + 2]);

        if (out_size >= NSPAN * LL) {
            d_out[sp * LL + 0] = x0;
            d_out[sp * LL + 1] = x1;
            d_out[sp * LL + 2] = x2;
        }

        const float m   = fmaxf(x0, fmaxf(x1, x2));
        const float lse = m + logf(expf(x0 - m) + expf(x1 - m) + expf(x2 - m));
        const bool valid = (lab >= 0);
        const float xl = valid ? ((lab == 0) ? x0 : ((lab == 1) ? x1 : x2)) : 0.f;
        nll += valid ? (lse - xl) : 0.f;
        vf  += valid ? 1.f : 0.f;
    }

    // block-wide reduce (8 warps)
    #pragma unroll
    for (int o = 16; o > 0; o >>= 1) {
        nll += __shfl_down_sync(0xffffffffu, nll, o);
        vf  += __shfl_down_sync(0xffffffffu, vf,  o);
    }
    __shared__ float s_n[8], s_v[8];
    const int w = t >> 5, lane = t & 31;
    if (lane == 0) { s_n[w] = nll; s_v[w] = vf; }
    __syncthreads();
    if (t == 0) {
        float a = 0.f, v = 0.f;
        #pragma unroll
        for (int k = 0; k < 8; k++) { a += s_n[k]; v += s_v[k]; }
        const float loss = a / v;
        if (out_size >= NSPAN * LL + 1)  d_out[NSPAN * LL] = loss;
        else if (out_size < NSPAN * LL)  d_out[0] = loss;
    }
}

extern "C" void kernel_launch(void* const* d_in, const int* in_sizes, int n_in,
                              void* d_out, int out_size)
{
    const float* enc  = (const float*)d_in[0];   // encoder_layer (BS,S,H) f32
    const float* W    = (const float*)d_in[1];   // (C,H,L) f32
    const float* bias = (const float*)d_in[2];   // (C,L)   f32
    const void*  head = d_in[3];                 // (BS,D) int32 or int64
    const void*  tail = d_in[4];
    const void*  dtid = d_in[5];
    const void*  labs = d_in[6];

    fused_kernel<<<NBLK, 256>>>(enc, W, bias, head, tail, dtid, labs,
                                (float*)d_out, out_size);
}

// round 4
// speedup vs baseline: 1.0620x; 1.0011x over previous
#include <cuda_runtime.h>

#define BS 16
#define SS 2048
#define HH 1024
#define DD 32
#define CC 8
#define LL 3
#define NSPAN (BS * DD)     // 512
#define NBLK  (NSPAN * 2)   // 1024 — two half-span blocks per span

// partial logits per block (block = 2*span + half), rewritten every launch
__device__ float g_part[NBLK * LL];
// completion counter for last-block-done combine (reset by the tail block)
__device__ unsigned int g_count = 0;

__device__ __forceinline__ int load_int(const void* p, int i, bool is64) {
    if (is64) return (int)((const long long*)p)[i];
    return ((const int*)p)[i];
}

// Fused kernel: grid = 1024, block = 256. NO min-blocks reg cap — ILP > occupancy
// for this HBM stream (R3 post-mortem: 32-reg cap collapsed per-thread MLP).
__global__ void __launch_bounds__(256)
fused_kernel(const float* __restrict__ enc,
             const float* __restrict__ W,
             const float* __restrict__ bias,
             const void* __restrict__ headp,
             const void* __restrict__ tailp,
             const void* __restrict__ dtp,
             const void* __restrict__ labp,
             float* __restrict__ d_out, int out_size)
{
    const int blk  = blockIdx.x;
    const int span = blk >> 1;
    const int half = blk & 1;
    const int t    = threadIdx.x;      // 0..255

    // ---- parallel int32-vs-int64 layout detection (odd high-words all zero) ----
    __shared__ int s_flags;
    if (t == 0) s_flags = 0;
    __syncthreads();
    {
        const int w = 2 * t + 1;       // odd words 1..511
        int f = 0;
        if (((const int*)headp)[w]) f |= 1;
        if (((const int*)tailp)[w]) f |= 2;
        if (((const int*)dtp)[w])   f |= 4;
        if (((const int*)labp)[w])  f |= 8;
        if (f) atomicOr(&s_flags, f);
    }
    __syncthreads();
    const int flags = s_flags;
    const bool h64 = !(flags & 1);
    const bool t64 = !(flags & 2);
    const bool c64 = !(flags & 4);
    const bool l64 = !(flags & 8);

    const int s0 = load_int(headp, span, h64) + 1;     // mask starts at head+1
    const int n  = load_int(tailp, span, t64) - s0;    // typically 63
    const int c  = load_int(dtp,   span, c64);
    const int b  = span / DD;

    // this half's row range
    const int hn = (n + 1) >> 1;
    const int r0 = half * hn;
    const int r1 = (r0 + hn < n) ? (r0 + hn) : n;
    const int nr = r1 - r0;

    const float4* base =
        (const float4*)(enc + ((size_t)b * SS + (size_t)(s0 + r0)) * HH) + t;
    const int rowstep = HH / 4;

    float4 acc = make_float4(0.f, 0.f, 0.f, 0.f);
    int i = 0;
    for (; i + 4 <= nr; i += 4) {      // 4 independent LDG.128 in flight
        float4 v0 = __ldcs(base + (size_t)(i + 0) * rowstep);
        float4 v1 = __ldcs(base + (size_t)(i + 1) * rowstep);
        float4 v2 = __ldcs(base + (size_t)(i + 2) * rowstep);
        float4 v3 = __ldcs(base + (size_t)(i + 3) * rowstep);
        acc.x += (v0.x + v1.x) + (v2.x + v3.x);
        acc.y += (v0.y + v1.y) + (v2.y + v3.y);
        acc.z += (v0.z + v1.z) + (v2.z + v3.z);
        acc.w += (v0.w + v1.w) + (v2.w + v3.w);
    }
    for (; i < nr; i++) {
        float4 v = __ldcs(base + (size_t)i * rowstep);
        acc.x += v.x; acc.y += v.y; acc.z += v.z; acc.w += v.w;
    }

    // partial GEMV against W[c] (un-normalized, no bias — linear)
    const int h0 = t * 4;
    const float* Wc = W + (size_t)c * HH * LL;

    float l0 = acc.x * __ldg(&Wc[(h0 + 0) * LL + 0]) + acc.y * __ldg(&Wc[(h0 + 1) * LL + 0])
             + acc.z * __ldg(&Wc[(h0 + 2) * LL + 0]) + acc.w * __ldg(&Wc[(h0 + 3) * LL + 0]);
    float l1 = acc.x * __ldg(&Wc[(h0 + 0) * LL + 1]) + acc.y * __ldg(&Wc[(h0 + 1) * LL + 1])
             + acc.z * __ldg(&Wc[(h0 + 2) * LL + 1]) + acc.w * __ldg(&Wc[(h0 + 3) * LL + 1]);
    float l2 = acc.x * __ldg(&Wc[(h0 + 0) * LL + 2]) + acc.y * __ldg(&Wc[(h0 + 1) * LL + 2])
             + acc.z * __ldg(&Wc[(h0 + 2) * LL + 2]) + acc.w * __ldg(&Wc[(h0 + 3) * LL + 2]);

    #pragma unroll
    for (int o = 16; o > 0; o >>= 1) {
        l0 += __shfl_down_sync(0xffffffffu, l0, o);
        l1 += __shfl_down_sync(0xffffffffu, l1, o);
        l2 += __shfl_down_sync(0xffffffffu, l2, o);
    }

    __shared__ float sred[8][3];
    {
        const int w = t >> 5, lane = t & 31;
        if (lane == 0) { sred[w][0] = l0; sred[w][1] = l1; sred[w][2] = l2; }
    }
    __syncthreads();

    if (t < LL) {
        float s = 0.f;
        #pragma unroll
        for (int k = 0; k < 8; k++) s += sred[k][t];
        g_part[blk * LL + t] = s;
    }

    // ---- last-block-done: elect the final block to combine ----
    __shared__ int s_last;
    __threadfence();                   // publish g_part before signaling
    __syncthreads();
    if (t == 0) {
        unsigned int prev = atomicAdd(&g_count, 1u);
        s_last = (prev == NBLK - 1) ? 1 : 0;
    }
    __syncthreads();
    if (!s_last) return;

    if (t == 0) g_count = 0;           // reset for next graph replay

    // ---- Phase 2: combine + loss (one block, 256 threads, 2 spans each) ----
    float nll = 0.f, vf = 0.f;
    #pragma unroll
    for (int k = 0; k < 2; k++) {
        const int sp = t + k * 256;    // span 0..511

        const int ss0 = load_int(headp, sp, h64) + 1;
        const int sn  = load_int(tailp, sp, t64) - ss0;
        const int sc  = load_int(dtp,   sp, c64);
        const int lab = load_int(labp,  sp, l64);

        const float inv = 1.0f / (float)sn;
        const float* pa = &g_part[(2 * sp) * LL];
        const float* pb = &g_part[(2 * sp + 1) * LL];
        const float x0 = (pa[0] + pb[0]) * inv + __ldg(&bias[sc * LL + 0]);
        const float x1 = (pa[1] + pb[1]) * inv + __ldg(&bias[sc * LL + 1]);
        const float x2 = (pa[2] + pb[2]) * inv + __ldg(&bias[sc * LL + 2]);

        if (out_size >= NSPAN * LL) {
            d_out[sp * LL + 0] = x0;
            d_out[sp * LL + 1] = x1;
            d_out[sp * LL + 2] = x2;
        }

        const float m   = fmaxf(x0, fmaxf(x1, x2));
        const float lse = m + logf(expf(x0 - m) + expf(x1 - m) + expf(x2 - m));
        const bool valid = (lab >= 0);
        const float xl = valid ? ((lab == 0) ? x0 : ((lab == 1) ? x1 : x2)) : 0.f;
        nll += valid ? (lse - xl) : 0.f;
        vf  += valid ? 1.f : 0.f;
    }

    #pragma unroll
    for (int o = 16; o > 0; o >>= 1) {
        nll += __shfl_down_sync(0xffffffffu, nll, o);
        vf  += __shfl_down_sync(0xffffffffu, vf,  o);
    }
    __shared__ float s_n[8], s_v[8];
    const int w = t >> 5, lane = t & 31;
    if (lane == 0) { s_n[w] = nll; s_v[w] = vf; }
    __syncthreads();
    if (t == 0) {
        float a = 0.f, v = 0.f;
        #pragma unroll
        for (int k = 0; k < 8; k++) { a += s_n[k]; v += s_v[k]; }
        const float loss = a / v;
        if (out_size >= NSPAN * LL + 1)  d_out[NSPAN * LL] = loss;
        else if (out_size < NSPAN * LL)  d_out[0] = loss;
    }
}

extern "C" void kernel_launch(void* const* d_in, const int* in_sizes, int n_in,
                              void* d_out, int out_size)
{
    const float* enc  = (const float*)d_in[0];   // encoder_layer (BS,S,H) f32
    const float* W    = (const float*)d_in[1];   // (C,H,L) f32
    const float* bias = (const float*)d_in[2];   // (C,L)   f32
    const void*  head = d_in[3];                 // (BS,D) int32 or int64
    const void*  tail = d_in[4];
    const void*  dtid = d_in[5];
    const void*  labs = d_in[6];

    fused_kernel<<<NBLK, 256>>>(enc, W, bias, head, tail, dtid, labs,
                                (float*)d_out, out_size);
}

// round 5
// speedup vs baseline: 1.0714x; 1.0088x over previous
#include <cuda_runtime.h>

#define BS 16
#define SS 2048
#define HH 1024
#define DD 32
#define CC 8
#define LL 3
#define NSPAN (BS * DD)     // 512
#define NBLK  (NSPAN * 2)   // 1024 — two half-span blocks per span

// partial logits per block (block = 2*span + half), rewritten every launch
__device__ float g_part[NBLK * LL];
// completion counter for last-block-done combine (reset by the tail block)
__device__ unsigned int g_count = 0;

__device__ __forceinline__ int load_int(const void* p, int i, bool is64) {
    if (is64) return (int)((const long long*)p)[i];
    return ((const int*)p)[i];
}

// Fused kernel: grid = 1024, block = 256. NO min-blocks reg cap — ILP > occupancy
// for this HBM stream (R3 post-mortem: 32-reg cap collapsed per-thread MLP).
__global__ void __launch_bounds__(256)
fused_kernel(const float* __restrict__ enc,
             const float* __restrict__ W,
             const float* __restrict__ bias,
             const void* __restrict__ headp,
             const void* __restrict__ tailp,
             const void* __restrict__ dtp,
             const void* __restrict__ labp,
             float* __restrict__ d_out, int out_size)
{
    const int blk  = blockIdx.x;
    const int span = blk >> 1;
    const int half = blk & 1;
    const int t    = threadIdx.x;      // 0..255

    // ---- parallel int32-vs-int64 layout detection (odd high-words all zero) ----
    __shared__ int s_flags;
    if (t == 0) s_flags = 0;
    __syncthreads();
    {
        const int w = 2 * t + 1;       // odd words 1..511
        int f = 0;
        if (((const int*)headp)[w]) f |= 1;
        if (((const int*)tailp)[w]) f |= 2;
        if (((const int*)dtp)[w])   f |= 4;
        if (((const int*)labp)[w])  f |= 8;
        if (f) atomicOr(&s_flags, f);
    }
    __syncthreads();
    const int flags = s_flags;
    const bool h64 = !(flags & 1);
    const bool t64 = !(flags & 2);
    const bool c64 = !(flags & 4);
    const bool l64 = !(flags & 8);

    const int s0 = load_int(headp, span, h64) + 1;     // mask starts at head+1
    const int n  = load_int(tailp, span, t64) - s0;    // typically 63
    const int c  = load_int(dtp,   span, c64);
    const int b  = span / DD;

    // this half's row range
    const int hn = (n + 1) >> 1;
    const int r0 = half * hn;
    const int r1 = (r0 + hn < n) ? (r0 + hn) : n;
    const int nr = r1 - r0;

    const float4* base =
        (const float4*)(enc + ((size_t)b * SS + (size_t)(s0 + r0)) * HH) + t;
    const int rowstep = HH / 4;

    float4 acc = make_float4(0.f, 0.f, 0.f, 0.f);
    int i = 0;
    for (; i + 4 <= nr; i += 4) {      // 4 independent LDG.128 in flight
        float4 v0 = __ldcs(base + (size_t)(i + 0) * rowstep);
        float4 v1 = __ldcs(base + (size_t)(i + 1) * rowstep);
        float4 v2 = __ldcs(base + (size_t)(i + 2) * rowstep);
        float4 v3 = __ldcs(base + (size_t)(i + 3) * rowstep);
        acc.x += (v0.x + v1.x) + (v2.x + v3.x);
        acc.y += (v0.y + v1.y) + (v2.y + v3.y);
        acc.z += (v0.z + v1.z) + (v2.z + v3.z);
        acc.w += (v0.w + v1.w) + (v2.w + v3.w);
    }
    for (; i < nr; i++) {
        float4 v = __ldcs(base + (size_t)i * rowstep);
        acc.x += v.x; acc.y += v.y; acc.z += v.z; acc.w += v.w;
    }

    // partial GEMV against W[c] (un-normalized, no bias — linear)
    const int h0 = t * 4;
    const float* Wc = W + (size_t)c * HH * LL;

    float l0 = acc.x * __ldg(&Wc[(h0 + 0) * LL + 0]) + acc.y * __ldg(&Wc[(h0 + 1) * LL + 0])
             + acc.z * __ldg(&Wc[(h0 + 2) * LL + 0]) + acc.w * __ldg(&Wc[(h0 + 3) * LL + 0]);
    float l1 = acc.x * __ldg(&Wc[(h0 + 0) * LL + 1]) + acc.y * __ldg(&Wc[(h0 + 1) * LL + 1])
             + acc.z * __ldg(&Wc[(h0 + 2) * LL + 1]) + acc.w * __ldg(&Wc[(h0 + 3) * LL + 1]);
    float l2 = acc.x * __ldg(&Wc[(h0 + 0) * LL + 2]) + acc.y * __ldg(&Wc[(h0 + 1) * LL + 2])
             + acc.z * __ldg(&Wc[(h0 + 2) * LL + 2]) + acc.w * __ldg(&Wc[(h0 + 3) * LL + 2]);

    #pragma unroll
    for (int o = 16; o > 0; o >>= 1) {
        l0 += __shfl_down_sync(0xffffffffu, l0, o);
        l1 += __shfl_down_sync(0xffffffffu, l1, o);
        l2 += __shfl_down_sync(0xffffffffu, l2, o);
    }

    __shared__ float sred[8][3];
    {
        const int w = t >> 5, lane = t & 31;
        if (lane == 0) { sred[w][0] = l0; sred[w][1] = l1; sred[w][2] = l2; }
    }
    __syncthreads();

    if (t < LL) {
        float s = 0.f;
        #pragma unroll
        for (int k = 0; k < 8; k++) s += sred[k][t];
        g_part[blk * LL + t] = s;
    }

    // ---- last-block-done: elect the final block to combine ----
    __shared__ int s_last;
    __threadfence();                   // publish g_part before signaling
    __syncthreads();
    if (t == 0) {
        unsigned int prev = atomicAdd(&g_count, 1u);
        s_last = (prev == NBLK - 1) ? 1 : 0;
    }
    __syncthreads();
    if (!s_last) return;

    if (t == 0) g_count = 0;           // reset for next graph replay

    // ---- Phase 2: combine + loss (one block, 256 threads, 2 spans each) ----
    float nll = 0.f, vf = 0.f;
    #pragma unroll
    for (int k = 0; k < 2; k++) {
        const int sp = t + k * 256;    // span 0..511

        const int ss0 = load_int(headp, sp, h64) + 1;
        const int sn  = load_int(tailp, sp, t64) - ss0;
        const int sc  = load_int(dtp,   sp, c64);
        const int lab = load_int(labp,  sp, l64);

        const float inv = 1.0f / (float)sn;
        const float* pa = &g_part[(2 * sp) * LL];
        const float* pb = &g_part[(2 * sp + 1) * LL];
        const float x0 = (pa[0] + pb[0]) * inv + __ldg(&bias[sc * LL + 0]);
        const float x1 = (pa[1] + pb[1]) * inv + __ldg(&bias[sc * LL + 1]);
        const float x2 = (pa[2] + pb[2]) * inv + __ldg(&bias[sc * LL + 2]);

        if (out_size >= NSPAN * LL) {
            d_out[sp * LL + 0] = x0;
            d_out[sp * LL + 1] = x1;
            d_out[sp * LL + 2] = x2;
        }

        const float m   = fmaxf(x0, fmaxf(x1, x2));
        const float lse = m + logf(expf(x0 - m) + expf(x1 - m) + expf(x2 - m));
        const bool valid = (lab >= 0);
        const float xl = valid ? ((lab == 0) ? x0 : ((lab == 1) ? x1 : x2)) : 0.f;
        nll += valid ? (lse - xl) : 0.f;
        vf  += valid ? 1.f : 0.f;
    }

    #pragma unroll
    for (int o = 16; o > 0; o >>= 1) {
        nll += __shfl_down_sync(0xffffffffu, nll, o);
        vf  += __shfl_down_sync(0xffffffffu, vf,  o);
    }
    __shared__ float s_n[8], s_v[8];
    const int w = t >> 5, lane = t & 31;
    if (lane == 0) { s_n[w] = nll; s_v[w] = vf; }
    __syncthreads();
    if (t == 0) {
        float a = 0.f, v = 0.f;
        #pragma unroll
        for (int k = 0; k < 8; k++) { a += s_n[k]; v += s_v[k]; }
        const float loss = a / v;
        if (out_size >= NSPAN * LL + 1)  d_out[NSPAN * LL] = loss;
        else if (out_size < NSPAN * LL)  d_out[0] = loss;
    }
}

extern "C" void kernel_launch(void* const* d_in, const int* in_sizes, int n_in,
                              void* d_out, int out_size)
{
    const float* enc  = (const float*)d_in[0];   // encoder_layer (BS,S,H) f32
    const float* W    = (const float*)d_in[1];   // (C,H,L) f32
    const float* bias = (const float*)d_in[2];   // (C,L)   f32
    const void*  head = d_in[3];                 // (BS,D) int32 or int64
    const void*  tail = d_in[4];
    const void*  dtid = d_in[5];
    const void*  labs = d_in[6];

    fused_kernel<<<NBLK, 256>>>(enc, W, bias, head, tail, dtid, labs,
                                (float*)d_out, out_size);
}